// round 4
// baseline (speedup 1.0000x reference)
#include <cuda_runtime.h>
#include <cuda_fp16.h>
#include <cstdint>

#define BATCH 2
#define CH    256
#define CI    128
#define NPOS  8192
#define NBLK  128   // NPOS / 64

// ---------------- scratch (static __device__, no allocations) ----------------
__device__ __half Qg [(size_t)BATCH*NPOS*CI];   // [b][n][ci]
__device__ __half Kg2[(size_t)BATCH*NPOS*CI];   // [b][n][ci]
__device__ __half Vg [(size_t)BATCH*CI*NPOS];   // [b][ci][n]  (transposed)
__device__ __half Yg [(size_t)BATCH*NPOS*CI];   // [b][n][ci]
__device__ float  wyg[(size_t)BATCH*CH*NPOS];   // [b][c][n]
__device__ float  psum_g[BATCH*NBLK*CH];
__device__ float  psq_g [BATCH*NBLK*CH];
__device__ float  scale_g[CH];
__device__ float  shift_g[CH];

// ---------------- helpers ----------------
__device__ __forceinline__ uint32_t packh2(float a, float b) {
    __half2 h = __floats2half2_rn(a, b);
    return *reinterpret_cast<uint32_t*>(&h);
}
__device__ __forceinline__ void mma16816(float* c, const uint32_t* a,
                                         uint32_t b0, uint32_t b1) {
    asm volatile(
        "mma.sync.aligned.m16n8k16.row.col.f32.f16.f16.f32 "
        "{%0,%1,%2,%3},{%4,%5,%6,%7},{%8,%9},{%0,%1,%2,%3};\n"
        : "+f"(c[0]), "+f"(c[1]), "+f"(c[2]), "+f"(c[3])
        : "r"(a[0]), "r"(a[1]), "r"(a[2]), "r"(a[3]), "r"(b0), "r"(b1));
}
__device__ __forceinline__ void cp16(uint32_t dst_s, const void* src_g) {
    asm volatile("cp.async.cg.shared.global [%0], [%1], 16;\n"
                 :: "r"(dst_s), "l"(src_g));
}
__device__ __forceinline__ void cp_commit_wait_all() {
    asm volatile("cp.async.commit_group;\n");
    asm volatile("cp.async.wait_group 0;\n");
}

// ============================================================================
// Kernel 1: fused theta/phi/g projections.
// out[n][oc] = sum_c x[b][c][n] * Wcat[oc][c] + bias,  oc in [0,384)
// Block: 64 n-positions, 256 threads (8 warps). Warp (mw = w&3) owns m16 tile,
// (ow = w>>2) owns 192-oc half (24 n8 tiles).
// ============================================================================
__global__ void __launch_bounds__(256)
proj_kernel(const float* __restrict__ x,
            const float* __restrict__ Wt, const float* __restrict__ bt,
            const float* __restrict__ Wp, const float* __restrict__ bp,
            const float* __restrict__ Wg, const float* __restrict__ bg)
{
    __shared__ __half Ws[384 * 40];  // [oc][c_chunk], stride 40 (conflict-free)
    __shared__ __half Xs[64 * 40];   // [n_local][c_chunk]

    const int tid  = threadIdx.x;
    const int w    = tid >> 5;
    const int lane = tid & 31;
    const int g = lane >> 2, t = lane & 3;
    const int b  = blockIdx.y;
    const int n0 = blockIdx.x * 64;
    const int mw = w & 3;
    const int ow = w >> 2;

    float acc[24][4];
#pragma unroll
    for (int i = 0; i < 24; i++) { acc[i][0]=acc[i][1]=acc[i][2]=acc[i][3]=0.f; }

    for (int kc = 0; kc < CH; kc += 32) {
        __syncthreads();
        // W chunk [384][32] -> fp16
#pragma unroll
        for (int it = 0; it < 24; it++) {
            int p = tid + 256 * it;
            int row = p >> 4, c2 = p & 15;
            const float* src; int r = row;
            if (row < 128)      { src = Wt; }
            else if (row < 256) { src = Wp; r = row - 128; }
            else                { src = Wg; r = row - 256; }
            float2 v = *reinterpret_cast<const float2*>(&src[r * CH + kc + 2 * c2]);
            *reinterpret_cast<uint32_t*>(&Ws[row * 40 + 2 * c2]) = packh2(v.x, v.y);
        }
        // x chunk [32 c][64 n] -> Xs[n][c] (transpose)
#pragma unroll
        for (int it = 0; it < 4; it++) {
            int p = tid + 256 * it;
            int cl = p >> 5, j2 = p & 31;
            float2 v = *reinterpret_cast<const float2*>(
                &x[((size_t)(b * CH + kc + cl)) * NPOS + n0 + 2 * j2]);
            Xs[(2 * j2)     * 40 + cl] = __float2half_rn(v.x);
            Xs[(2 * j2 + 1) * 40 + cl] = __float2half_rn(v.y);
        }
        __syncthreads();
#pragma unroll
        for (int ks = 0; ks < 2; ks++) {
            uint32_t a[4];
            int base = (mw * 16 + g) * 40 + ks * 16 + 2 * t;
            a[0] = *reinterpret_cast<const uint32_t*>(&Xs[base]);
            a[1] = *reinterpret_cast<const uint32_t*>(&Xs[base + 8 * 40]);
            a[2] = *reinterpret_cast<const uint32_t*>(&Xs[base + 8]);
            a[3] = *reinterpret_cast<const uint32_t*>(&Xs[base + 8 * 40 + 8]);
#pragma unroll
            for (int i = 0; i < 24; i++) {
                int ocr = (ow * 24 + i) * 8 + g;
                uint32_t b0 = *reinterpret_cast<const uint32_t*>(&Ws[ocr * 40 + ks * 16 + 2 * t]);
                uint32_t b1 = *reinterpret_cast<const uint32_t*>(&Ws[ocr * 40 + ks * 16 + 2 * t + 8]);
                mma16816(acc[i], a, b0, b1);
            }
        }
    }
    // epilogue: + bias, scatter to Q/K (row-major) and V (transposed), fp16
    const int row_lo = n0 + mw * 16 + g;
    const int row_hi = row_lo + 8;
#pragma unroll
    for (int i = 0; i < 24; i++) {
        int col0 = ow * 192 + i * 8 + 2 * t;
        int arr  = col0 >> 7;        // 0=theta(Q) 1=phi(K) 2=g(V)
        int ch   = col0 & 127;
        const float* bias = (arr == 0) ? bt : (arr == 1) ? bp : bg;
        float b0v = bias[ch], b1v = bias[ch + 1];
        float v0 = acc[i][0] + b0v, v1 = acc[i][1] + b1v;
        float v2 = acc[i][2] + b0v, v3 = acc[i][3] + b1v;
        if (arr == 2) {
            size_t base = ((size_t)b * CI + ch) * NPOS;
            Vg[base + row_lo]        = __float2half_rn(v0);
            Vg[base + NPOS + row_lo] = __float2half_rn(v1);
            Vg[base + row_hi]        = __float2half_rn(v2);
            Vg[base + NPOS + row_hi] = __float2half_rn(v3);
        } else {
            __half* dst = (arr == 0) ? Qg : Kg2;
            *reinterpret_cast<uint32_t*>(&dst[((size_t)b * NPOS + row_lo) * CI + ch]) = packh2(v0, v1);
            *reinterpret_cast<uint32_t*>(&dst[((size_t)b * NPOS + row_hi) * CI + ch]) = packh2(v2, v3);
        }
    }
}

// ============================================================================
// Kernel 2: flash attention (no scaling, no max-subtraction — logits are
// O(1), exp <= ~1e4, safe in fp16/fp32 without rescaling).
// Block = 128 q rows, 128 threads (4 warps). Each warp owns 32 q rows
// (2 m16 tiles) so every K/V B-fragment read from smem feeds TWO mmas.
// K/V tiles stream via cp.async (no RF staging -> no spill pressure).
// ============================================================================
__global__ void __launch_bounds__(128)
attn_kernel()
{
    __shared__ __half Ks[64 * 136];   // K tile [kv][ci]; also Q staging
    __shared__ __half Vs[128 * 72];   // V tile [ci][kv]

    const int tid  = threadIdx.x;
    const int w    = tid >> 5;
    const int lane = tid & 31;
    const int g = lane >> 2, t = lane & 3;
    const int b  = blockIdx.y;
    const int q0 = blockIdx.x * 128;

    const uint32_t Ks_s = (uint32_t)__cvta_generic_to_shared(Ks);
    const uint32_t Vs_s = (uint32_t)__cvta_generic_to_shared(Vs);

    // per-thread copy geometry (reused every tile)
    const int krow = tid >> 1, kc0 = (tid & 1) * 64;            // K: 128B per thread
    const uint32_t kdst = Ks_s + (krow * 136 + kc0) * 2;
    const uint32_t vdst = Vs_s + (tid * 72) * 2;

    // ---- stage Q (128 rows) through Ks in two halves; pull A-frags ----
    uint32_t Qf[2][8][4];
#pragma unroll
    for (int half = 0; half < 2; half++) {
        __syncthreads();
        {
            const __half* src = &Qg[((size_t)b * NPOS + q0 + half * 64 + krow) * CI + kc0];
#pragma unroll
            for (int i = 0; i < 8; i++) cp16(kdst + i * 16, src + i * 8);
            cp_commit_wait_all();
        }
        __syncthreads();
        if ((w >> 1) == half) {
#pragma unroll
            for (int sub = 0; sub < 2; sub++) {
                int ar = (w & 1) * 32 + sub * 16 + g;
#pragma unroll
                for (int kc = 0; kc < 8; kc++) {
                    int base = ar * 136 + kc * 16 + 2 * t;
                    Qf[sub][kc][0] = *reinterpret_cast<const uint32_t*>(&Ks[base]);
                    Qf[sub][kc][1] = *reinterpret_cast<const uint32_t*>(&Ks[base + 8 * 136]);
                    Qf[sub][kc][2] = *reinterpret_cast<const uint32_t*>(&Ks[base + 8]);
                    Qf[sub][kc][3] = *reinterpret_cast<const uint32_t*>(&Ks[base + 8 * 136 + 8]);
                }
            }
        }
    }

    float Yacc[2][16][4];
#pragma unroll
    for (int s = 0; s < 2; s++)
#pragma unroll
        for (int i = 0; i < 16; i++) { Yacc[s][i][0]=Yacc[s][i][1]=Yacc[s][i][2]=Yacc[s][i][3]=0.f; }
    float dsum[2][2] = {{0.f, 0.f}, {0.f, 0.f}};   // [sub][lo/hi]

    for (int kt = 0; kt < NBLK; kt++) {
        __syncthreads();
        {   // K tile: 64 rows x 128 ci ; V tile: 128 ci rows x 64 kv
            const __half* ksrc = &Kg2[((size_t)b * NPOS + kt * 64 + krow) * CI + kc0];
            const __half* vsrc = &Vg[((size_t)b * CI + tid) * NPOS + kt * 64];
#pragma unroll
            for (int i = 0; i < 8; i++) cp16(kdst + i * 16, ksrc + i * 8);
#pragma unroll
            for (int i = 0; i < 8; i++) cp16(vdst + i * 16, vsrc + i * 8);
            cp_commit_wait_all();
        }
        __syncthreads();

        // process KV tile in k16 chunks: S(QK^T) -> exp -> PV, per chunk
#pragma unroll
        for (int j = 0; j < 4; j++) {
            float S2[2][2][4];
#pragma unroll
            for (int s = 0; s < 2; s++)
#pragma unroll
                for (int n2 = 0; n2 < 2; n2++) { S2[s][n2][0]=S2[s][n2][1]=S2[s][n2][2]=S2[s][n2][3]=0.f; }
#pragma unroll
            for (int kc = 0; kc < 8; kc++) {
#pragma unroll
                for (int n2 = 0; n2 < 2; n2++) {
                    int base = ((2 * j + n2) * 8 + g) * 136 + kc * 16 + 2 * t;
                    uint32_t b0 = *reinterpret_cast<const uint32_t*>(&Ks[base]);
                    uint32_t b1 = *reinterpret_cast<const uint32_t*>(&Ks[base + 8]);
                    mma16816(S2[0][n2], Qf[0][kc], b0, b1);
                    mma16816(S2[1][n2], Qf[1][kc], b0, b1);
                }
            }
            uint32_t Ap[2][4];
#pragma unroll
            for (int s = 0; s < 2; s++) {
                float e0 = __expf(S2[s][0][0]), e1 = __expf(S2[s][0][1]);
                float e2 = __expf(S2[s][0][2]), e3 = __expf(S2[s][0][3]);
                float f0 = __expf(S2[s][1][0]), f1 = __expf(S2[s][1][1]);
                float f2 = __expf(S2[s][1][2]), f3 = __expf(S2[s][1][3]);
                dsum[s][0] += e0 + e1 + f0 + f1;
                dsum[s][1] += e2 + e3 + f2 + f3;
                Ap[s][0] = packh2(e0, e1);
                Ap[s][1] = packh2(e2, e3);
                Ap[s][2] = packh2(f0, f1);
                Ap[s][3] = packh2(f2, f3);
            }
#pragma unroll
            for (int ct = 0; ct < 16; ct++) {
                int base = (ct * 8 + g) * 72 + j * 16 + 2 * t;
                uint32_t b0 = *reinterpret_cast<const uint32_t*>(&Vs[base]);
                uint32_t b1 = *reinterpret_cast<const uint32_t*>(&Vs[base + 8]);
                mma16816(Yacc[0][ct], Ap[0], b0, b1);
                mma16816(Yacc[1][ct], Ap[1], b0, b1);
            }
        }
    }

    // row sums: reduce over t (lanes sharing g differ in bits 0-1)
#pragma unroll
    for (int s = 0; s < 2; s++) {
#pragma unroll
        for (int h = 0; h < 2; h++) {
            dsum[s][h] += __shfl_xor_sync(0xffffffffu, dsum[s][h], 1);
            dsum[s][h] += __shfl_xor_sync(0xffffffffu, dsum[s][h], 2);
        }
    }

    // write Y fp16 [b][q][ci]
#pragma unroll
    for (int s = 0; s < 2; s++) {
        float rlo = 1.f / dsum[s][0], rhi = 1.f / dsum[s][1];
        size_t olo = ((size_t)b * NPOS + q0 + w * 32 + s * 16 + g) * CI;
        size_t ohi = olo + (size_t)8 * CI;
#pragma unroll
        for (int ct = 0; ct < 16; ct++) {
            int ch = ct * 8 + 2 * t;
            *reinterpret_cast<uint32_t*>(&Yg[olo + ch]) = packh2(Yacc[s][ct][0] * rlo, Yacc[s][ct][1] * rlo);
            *reinterpret_cast<uint32_t*>(&Yg[ohi + ch]) = packh2(Yacc[s][ct][2] * rhi, Yacc[s][ct][3] * rhi);
        }
    }
}

// ============================================================================
// Kernel 3: wy = Ww @ y + bw  -> wyg [b][256][n], plus per-block BN partials.
// Block: 64 n rows, 256 threads (8 warps): (mw = w&3) m16 tile, (ow = w>>2)
// 128-oc half (16 n8 tiles).
// ============================================================================
__global__ void __launch_bounds__(256)
wproj_kernel(const float* __restrict__ Ww, const float* __restrict__ bw)
{
    __shared__ __half Ys[64 * 136];
    __shared__ __half Ws2[256 * 40];
    __shared__ float  ps[4][256];
    __shared__ float  pq[4][256];

    const int tid  = threadIdx.x;
    const int w    = tid >> 5;
    const int lane = tid & 31;
    const int g = lane >> 2, t = lane & 3;
    const int b  = blockIdx.y;
    const int n0 = blockIdx.x * 64;
    const int mw = w & 3;
    const int ow = w >> 2;

    {   // Y tile [64][128]
        int row = tid >> 2, off = (tid & 3) * 32;
        const uint4* src = reinterpret_cast<const uint4*>(&Yg[((size_t)b * NPOS + n0 + row) * CI + off]);
        uint4* dst = reinterpret_cast<uint4*>(&Ys[row * 136 + off]);
#pragma unroll
        for (int i = 0; i < 4; i++) dst[i] = src[i];
    }

    float acc[16][4];
#pragma unroll
    for (int i = 0; i < 16; i++) { acc[i][0]=acc[i][1]=acc[i][2]=acc[i][3]=0.f; }

    for (int kc = 0; kc < CI; kc += 32) {
        __syncthreads();
#pragma unroll
        for (int it = 0; it < 16; it++) {
            int p = tid + 256 * it;
            int oc = p >> 4, c2 = p & 15;
            float2 v = *reinterpret_cast<const float2*>(&Ww[oc * CI + kc + 2 * c2]);
            *reinterpret_cast<uint32_t*>(&Ws2[oc * 40 + 2 * c2]) = packh2(v.x, v.y);
        }
        __syncthreads();
#pragma unroll
        for (int ks = 0; ks < 2; ks++) {
            uint32_t a[4];
            int base = (mw * 16 + g) * 136 + kc + ks * 16 + 2 * t;
            a[0] = *reinterpret_cast<const uint32_t*>(&Ys[base]);
            a[1] = *reinterpret_cast<const uint32_t*>(&Ys[base + 8 * 136]);
            a[2] = *reinterpret_cast<const uint32_t*>(&Ys[base + 8]);
            a[3] = *reinterpret_cast<const uint32_t*>(&Ys[base + 8 * 136 + 8]);
#pragma unroll
            for (int i = 0; i < 16; i++) {
                int ocr = (ow * 16 + i) * 8 + g;
                uint32_t b0 = *reinterpret_cast<const uint32_t*>(&Ws2[ocr * 40 + ks * 16 + 2 * t]);
                uint32_t b1 = *reinterpret_cast<const uint32_t*>(&Ws2[ocr * 40 + ks * 16 + 2 * t + 8]);
                mma16816(acc[i], a, b0, b1);
            }
        }
    }
    // epilogue: bias, store wy fp32, per-warp BN partials (deterministic)
    const int row_lo = n0 + mw * 16 + g;
    const int row_hi = row_lo + 8;
#pragma unroll
    for (int i = 0; i < 16; i++) {
        int oc0 = ow * 128 + i * 8 + 2 * t;
        float bw0 = bw[oc0], bw1 = bw[oc0 + 1];
        float v0 = acc[i][0] + bw0, v1 = acc[i][1] + bw1;
        float v2 = acc[i][2] + bw0, v3 = acc[i][3] + bw1;
        size_t base = ((size_t)b * CH + oc0) * NPOS;
        wyg[base + row_lo]        = v0;
        wyg[base + NPOS + row_lo] = v1;
        wyg[base + row_hi]        = v2;
        wyg[base + NPOS + row_hi] = v3;
        float s0 = v0 + v2, s1 = v1 + v3;
        float q0s = v0 * v0 + v2 * v2, q1s = v1 * v1 + v3 * v3;
#pragma unroll
        for (int m = 4; m <= 16; m <<= 1) {
            s0  += __shfl_xor_sync(0xffffffffu, s0, m);
            s1  += __shfl_xor_sync(0xffffffffu, s1, m);
            q0s += __shfl_xor_sync(0xffffffffu, q0s, m);
            q1s += __shfl_xor_sync(0xffffffffu, q1s, m);
        }
        if (lane < 4) {  // g==0, t==lane
            int oc = ow * 128 + i * 8 + 2 * lane;
            ps[mw][oc] = s0;  ps[mw][oc + 1] = s1;
            pq[mw][oc] = q0s; pq[mw][oc + 1] = q1s;
        }
    }
    __syncthreads();
    {   // combine across m-tiles, store block partials
        float s = ps[0][tid] + ps[1][tid] + ps[2][tid] + ps[3][tid];
        float q = pq[0][tid] + pq[1][tid] + pq[2][tid] + pq[3][tid];
        int blk = blockIdx.y * NBLK + blockIdx.x;
        psum_g[blk * CH + tid] = s;
        psq_g [blk * CH + tid] = q;
    }
}

// ============================================================================
// Kernel 4: BN stats -> scale/shift (one block, deterministic)
// ============================================================================
__global__ void bnstats_kernel(const float* __restrict__ gamma,
                               const float* __restrict__ beta)
{
    int c = threadIdx.x;
    float s = 0.f, q = 0.f;
    for (int blk = 0; blk < BATCH * NBLK; blk++) {
        s += psum_g[blk * CH + c];
        q += psq_g [blk * CH + c];
    }
    const float inv = 1.f / (float)(BATCH * NPOS);
    float mean = s * inv;
    float var  = q * inv - mean * mean;
    float sc = gamma[c] * rsqrtf(var + 1e-5f);
    scale_g[c] = sc;
    shift_g[c] = beta[c] - mean * sc;
}

// ============================================================================
// Kernel 5: out = wy * scale + shift + x  (vectorized)
// ============================================================================
__global__ void __launch_bounds__(256)
final_kernel(const float* __restrict__ x, float* __restrict__ out)
{
    size_t e = ((size_t)blockIdx.x * 256 + threadIdx.x) * 4;
    int c = (int)((e >> 13) & 255);
    float4 wv = *reinterpret_cast<const float4*>(&wyg[e]);
    float4 xv = *reinterpret_cast<const float4*>(&x[e]);
    float sc = scale_g[c], sh = shift_g[c];
    float4 o;
    o.x = wv.x * sc + sh + xv.x;
    o.y = wv.y * sc + sh + xv.y;
    o.z = wv.z * sc + sh + xv.z;
    o.w = wv.w * sc + sh + xv.w;
    *reinterpret_cast<float4*>(&out[e]) = o;
}

// ============================================================================
extern "C" void kernel_launch(void* const* d_in, const int* in_sizes, int n_in,
                              void* d_out, int out_size)
{
    const float* x     = (const float*)d_in[0];
    const float* Wt    = (const float*)d_in[1];
    const float* bt    = (const float*)d_in[2];
    const float* Wp    = (const float*)d_in[3];
    const float* bp    = (const float*)d_in[4];
    const float* Wg    = (const float*)d_in[5];
    const float* bg    = (const float*)d_in[6];
    const float* Ww    = (const float*)d_in[7];
    const float* bw    = (const float*)d_in[8];
    const float* gamma = (const float*)d_in[9];
    const float* beta  = (const float*)d_in[10];
    float* out = (float*)d_out;

    proj_kernel<<<dim3(NBLK, BATCH), 256>>>(x, Wt, bt, Wp, bp, Wg, bg);
    attn_kernel<<<dim3(NPOS / 128, BATCH), 128>>>();
    wproj_kernel<<<dim3(NBLK, BATCH), 256>>>(Ww, bw);
    bnstats_kernel<<<1, CH>>>(gamma, beta);
    final_kernel<<<(BATCH * CH * NPOS) / (256 * 4), 256>>>(x, out);
}

// round 6
// speedup vs baseline: 1.1629x; 1.1629x over previous
#include <cuda_runtime.h>
#include <cuda_fp16.h>
#include <cstdint>

#define BATCH 2
#define CH    256
#define CI    128
#define NPOS  8192
#define NBLK  128   // NPOS / 64

// attention smem geometry (in __half units)
#define KS_H   (64 * 136)            // K tile [kv][ci], stride 136
#define VS_H   (128 * 72)            // V tile [ci][kv], stride 72
#define STAGE_H (KS_H + VS_H)        // one pipeline stage
#define ATTN_SMEM_BYTES (2 * STAGE_H * 2)   // 2 stages, 2B/half = 71680

// ---------------- scratch (static __device__, no allocations) ----------------
__device__ __half Qg [(size_t)BATCH*NPOS*CI];   // [b][n][ci]
__device__ __half Kg2[(size_t)BATCH*NPOS*CI];   // [b][n][ci]
__device__ __half Vg [(size_t)BATCH*CI*NPOS];   // [b][ci][n]  (transposed)
__device__ __half Yg [(size_t)BATCH*NPOS*CI];   // [b][n][ci]
__device__ float  wyg[(size_t)BATCH*CH*NPOS];   // [b][c][n]
__device__ float  psum_g[BATCH*NBLK*CH];
__device__ float  psq_g [BATCH*NBLK*CH];
__device__ float  scale_g[CH];
__device__ float  shift_g[CH];

// ---------------- helpers ----------------
__device__ __forceinline__ uint32_t packh2(float a, float b) {
    __half2 h = __floats2half2_rn(a, b);
    return *reinterpret_cast<uint32_t*>(&h);
}
__device__ __forceinline__ void mma16816(float* c, const uint32_t* a,
                                         uint32_t b0, uint32_t b1) {
    asm volatile(
        "mma.sync.aligned.m16n8k16.row.col.f32.f16.f16.f32 "
        "{%0,%1,%2,%3},{%4,%5,%6,%7},{%8,%9},{%0,%1,%2,%3};\n"
        : "+f"(c[0]), "+f"(c[1]), "+f"(c[2]), "+f"(c[3])
        : "r"(a[0]), "r"(a[1]), "r"(a[2]), "r"(a[3]), "r"(b0), "r"(b1));
}
__device__ __forceinline__ void cp16(uint32_t dst_s, const void* src_g) {
    asm volatile("cp.async.cg.shared.global [%0], [%1], 16;\n"
                 :: "r"(dst_s), "l"(src_g));
}
__device__ __forceinline__ void cp_commit() {
    asm volatile("cp.async.commit_group;\n");
}
__device__ __forceinline__ void cp_wait0() {
    asm volatile("cp.async.wait_group 0;\n");
}
__device__ __forceinline__ void cp_wait1() {
    asm volatile("cp.async.wait_group 1;\n");
}

// ============================================================================
// Kernel 1: fused theta/phi/g projections.
// out[n][oc] = sum_c x[b][c][n] * Wcat[oc][c] + bias,  oc in [0,384)
// Block: 64 n-positions, 256 threads (8 warps). Warp (mw = w&3) owns m16 tile,
// (ow = w>>2) owns 192-oc half (24 n8 tiles).
// ============================================================================
__global__ void __launch_bounds__(256)
proj_kernel(const float* __restrict__ x,
            const float* __restrict__ Wt, const float* __restrict__ bt,
            const float* __restrict__ Wp, const float* __restrict__ bp,
            const float* __restrict__ Wg, const float* __restrict__ bg)
{
    __shared__ __half Ws[384 * 40];  // [oc][c_chunk], stride 40 (conflict-free)
    __shared__ __half Xs[64 * 40];   // [n_local][c_chunk]

    const int tid  = threadIdx.x;
    const int w    = tid >> 5;
    const int lane = tid & 31;
    const int g = lane >> 2, t = lane & 3;
    const int b  = blockIdx.y;
    const int n0 = blockIdx.x * 64;
    const int mw = w & 3;
    const int ow = w >> 2;

    float acc[24][4];
#pragma unroll
    for (int i = 0; i < 24; i++) { acc[i][0]=acc[i][1]=acc[i][2]=acc[i][3]=0.f; }

    for (int kc = 0; kc < CH; kc += 32) {
        __syncthreads();
        // W chunk [384][32] -> fp16
#pragma unroll
        for (int it = 0; it < 24; it++) {
            int p = tid + 256 * it;
            int row = p >> 4, c2 = p & 15;
            const float* src; int r = row;
            if (row < 128)      { src = Wt; }
            else if (row < 256) { src = Wp; r = row - 128; }
            else                { src = Wg; r = row - 256; }
            float2 v = *reinterpret_cast<const float2*>(&src[r * CH + kc + 2 * c2]);
            *reinterpret_cast<uint32_t*>(&Ws[row * 40 + 2 * c2]) = packh2(v.x, v.y);
        }
        // x chunk [32 c][64 n] -> Xs[n][c] (transpose)
#pragma unroll
        for (int it = 0; it < 4; it++) {
            int p = tid + 256 * it;
            int cl = p >> 5, j2 = p & 31;
            float2 v = *reinterpret_cast<const float2*>(
                &x[((size_t)(b * CH + kc + cl)) * NPOS + n0 + 2 * j2]);
            Xs[(2 * j2)     * 40 + cl] = __float2half_rn(v.x);
            Xs[(2 * j2 + 1) * 40 + cl] = __float2half_rn(v.y);
        }
        __syncthreads();
#pragma unroll
        for (int ks = 0; ks < 2; ks++) {
            uint32_t a[4];
            int base = (mw * 16 + g) * 40 + ks * 16 + 2 * t;
            a[0] = *reinterpret_cast<const uint32_t*>(&Xs[base]);
            a[1] = *reinterpret_cast<const uint32_t*>(&Xs[base + 8 * 40]);
            a[2] = *reinterpret_cast<const uint32_t*>(&Xs[base + 8]);
            a[3] = *reinterpret_cast<const uint32_t*>(&Xs[base + 8 * 40 + 8]);
#pragma unroll
            for (int i = 0; i < 24; i++) {
                int ocr = (ow * 24 + i) * 8 + g;
                uint32_t b0 = *reinterpret_cast<const uint32_t*>(&Ws[ocr * 40 + ks * 16 + 2 * t]);
                uint32_t b1 = *reinterpret_cast<const uint32_t*>(&Ws[ocr * 40 + ks * 16 + 2 * t + 8]);
                mma16816(acc[i], a, b0, b1);
            }
        }
    }
    // epilogue: + bias, scatter to Q/K (row-major) and V (transposed), fp16
    const int row_lo = n0 + mw * 16 + g;
    const int row_hi = row_lo + 8;
#pragma unroll
    for (int i = 0; i < 24; i++) {
        int col0 = ow * 192 + i * 8 + 2 * t;
        int arr  = col0 >> 7;        // 0=theta(Q) 1=phi(K) 2=g(V)
        int ch   = col0 & 127;
        const float* bias = (arr == 0) ? bt : (arr == 1) ? bp : bg;
        float b0v = bias[ch], b1v = bias[ch + 1];
        float v0 = acc[i][0] + b0v, v1 = acc[i][1] + b1v;
        float v2 = acc[i][2] + b0v, v3 = acc[i][3] + b1v;
        if (arr == 2) {
            size_t base = ((size_t)b * CI + ch) * NPOS;
            Vg[base + row_lo]        = __float2half_rn(v0);
            Vg[base + NPOS + row_lo] = __float2half_rn(v1);
            Vg[base + row_hi]        = __float2half_rn(v2);
            Vg[base + NPOS + row_hi] = __float2half_rn(v3);
        } else {
            __half* dst = (arr == 0) ? Qg : Kg2;
            *reinterpret_cast<uint32_t*>(&dst[((size_t)b * NPOS + row_lo) * CI + ch]) = packh2(v0, v1);
            *reinterpret_cast<uint32_t*>(&dst[((size_t)b * NPOS + row_hi) * CI + ch]) = packh2(v2, v3);
        }
    }
}

// ============================================================================
// Kernel 2: flash attention (no scaling, no max-subtraction — logits are
// O(1), exp <= ~1e4, safe in fp16/fp32 without rescaling).
// Block = 128 q rows, 128 threads (4 warps). Each warp owns 32 q rows
// (2 m16 tiles) so every K/V B-fragment read from smem feeds TWO mmas.
// K/V tiles stream via a 2-stage cp.async pipeline (dynamic smem, 70KB).
// ============================================================================
__global__ void __launch_bounds__(128)
attn_kernel()
{
    extern __shared__ __half sm[];   // [2 stages][Ks 64x136 | Vs 128x72]

    const int tid  = threadIdx.x;
    const int w    = tid >> 5;
    const int lane = tid & 31;
    const int g = lane >> 2, t = lane & 3;
    const int b  = blockIdx.y;
    const int q0 = blockIdx.x * 128;

    const uint32_t sm_s = (uint32_t)__cvta_generic_to_shared(sm);

    // per-thread copy geometry (reused every tile)
    const int krow = tid >> 1, kc0 = (tid & 1) * 64;            // K: 128B/thread
    const uint32_t koff = (uint32_t)(krow * 136 + kc0) * 2;     // byte offsets within stage
    const uint32_t voff = (uint32_t)(KS_H + tid * 72) * 2;
    const size_t  kg_row = (size_t)b * NPOS;                    // Kg2 row base
    const size_t  vg_row = ((size_t)b * CI + tid) * NPOS;       // Vg row for this thread

    // ---- stage Q (128 rows) through stage-0 Ks; pull A-frags ----
    uint32_t Qf[2][8][4];
#pragma unroll
    for (int half = 0; half < 2; half++) {
        __syncthreads();
        {
            const __half* src = &Qg[(kg_row + q0 + half * 64 + krow) * CI + kc0];
#pragma unroll
            for (int i = 0; i < 8; i++) cp16(sm_s + koff + i * 16, src + i * 8);
            cp_commit(); cp_wait0();
        }
        __syncthreads();
        if ((w >> 1) == half) {
#pragma unroll
            for (int sub = 0; sub < 2; sub++) {
                int ar = (w & 1) * 32 + sub * 16 + g;
#pragma unroll
                for (int kc = 0; kc < 8; kc++) {
                    int base = ar * 136 + kc * 16 + 2 * t;
                    Qf[sub][kc][0] = *reinterpret_cast<const uint32_t*>(&sm[base]);
                    Qf[sub][kc][1] = *reinterpret_cast<const uint32_t*>(&sm[base + 8 * 136]);
                    Qf[sub][kc][2] = *reinterpret_cast<const uint32_t*>(&sm[base + 8]);
                    Qf[sub][kc][3] = *reinterpret_cast<const uint32_t*>(&sm[base + 8 * 136 + 8]);
                }
            }
        }
    }
    __syncthreads();   // Q frag reads done before tile 0 overwrites stage 0

    float Yacc[2][16][4];
#pragma unroll
    for (int s = 0; s < 2; s++)
#pragma unroll
        for (int i = 0; i < 16; i++) { Yacc[s][i][0]=Yacc[s][i][1]=Yacc[s][i][2]=Yacc[s][i][3]=0.f; }
    float dsum[2][2] = {{0.f, 0.f}, {0.f, 0.f}};   // [sub][lo/hi]

    // prime pipeline: tiles 0 and 1
#pragma unroll
    for (int pre = 0; pre < 2; pre++) {
        uint32_t sb = sm_s + pre * (STAGE_H * 2);
        const __half* ksrc = &Kg2[(kg_row + pre * 64 + krow) * CI + kc0];
        const __half* vsrc = &Vg[vg_row + pre * 64];
#pragma unroll
        for (int i = 0; i < 8; i++) cp16(sb + koff + i * 16, ksrc + i * 8);
#pragma unroll
        for (int i = 0; i < 8; i++) cp16(sb + voff + i * 16, vsrc + i * 8);
        cp_commit();
    }

    for (int kt = 0; kt < NBLK; kt++) {
        const __half* Ks = sm + (kt & 1) * STAGE_H;
        const __half* Vs = Ks + KS_H;

        if (kt < NBLK - 1) cp_wait1(); else cp_wait0();   // tile kt resident
        __syncthreads();

        // process KV tile in k16 chunks: S(QK^T) -> exp -> PV, per chunk
#pragma unroll
        for (int j = 0; j < 4; j++) {
            float S2[2][2][4];
#pragma unroll
            for (int s = 0; s < 2; s++)
#pragma unroll
                for (int n2 = 0; n2 < 2; n2++) { S2[s][n2][0]=S2[s][n2][1]=S2[s][n2][2]=S2[s][n2][3]=0.f; }
#pragma unroll
            for (int kc = 0; kc < 8; kc++) {
#pragma unroll
                for (int n2 = 0; n2 < 2; n2++) {
                    int base = ((2 * j + n2) * 8 + g) * 136 + kc * 16 + 2 * t;
                    uint32_t b0 = *reinterpret_cast<const uint32_t*>(&Ks[base]);
                    uint32_t b1 = *reinterpret_cast<const uint32_t*>(&Ks[base + 8]);
                    mma16816(S2[0][n2], Qf[0][kc], b0, b1);
                    mma16816(S2[1][n2], Qf[1][kc], b0, b1);
                }
            }
            uint32_t Ap[2][4];
#pragma unroll
            for (int s = 0; s < 2; s++) {
                float e0 = __expf(S2[s][0][0]), e1 = __expf(S2[s][0][1]);
                float e2 = __expf(S2[s][0][2]), e3 = __expf(S2[s][0][3]);
                float f0 = __expf(S2[s][1][0]), f1 = __expf(S2[s][1][1]);
                float f2 = __expf(S2[s][1][2]), f3 = __expf(S2[s][1][3]);
                dsum[s][0] += e0 + e1 + f0 + f1;
                dsum[s][1] += e2 + e3 + f2 + f3;
                Ap[s][0] = packh2(e0, e1);
                Ap[s][1] = packh2(e2, e3);
                Ap[s][2] = packh2(f0, f1);
                Ap[s][3] = packh2(f2, f3);
            }
#pragma unroll
            for (int ct = 0; ct < 16; ct++) {
                int base = (ct * 8 + g) * 72 + j * 16 + 2 * t;
                uint32_t b0 = *reinterpret_cast<const uint32_t*>(&Vs[base]);
                uint32_t b1 = *reinterpret_cast<const uint32_t*>(&Vs[base + 8]);
                mma16816(Yacc[0][ct], Ap[0], b0, b1);
                mma16816(Yacc[1][ct], Ap[1], b0, b1);
            }
        }
        __syncthreads();   // all warps done with this stage before refill

        if (kt + 2 < NBLK) {   // prefetch tile kt+2 into the stage just freed
            uint32_t sb = sm_s + (kt & 1) * (STAGE_H * 2);
            const __half* ksrc = &Kg2[(kg_row + (kt + 2) * 64 + krow) * CI + kc0];
            const __half* vsrc = &Vg[vg_row + (kt + 2) * 64];
#pragma unroll
            for (int i = 0; i < 8; i++) cp16(sb + koff + i * 16, ksrc + i * 8);
#pragma unroll
            for (int i = 0; i < 8; i++) cp16(sb + voff + i * 16, vsrc + i * 8);
            cp_commit();
        }
    }

    // row sums: reduce over t (lanes sharing g differ in bits 0-1)
#pragma unroll
    for (int s = 0; s < 2; s++) {
#pragma unroll
        for (int h = 0; h < 2; h++) {
            dsum[s][h] += __shfl_xor_sync(0xffffffffu, dsum[s][h], 1);
            dsum[s][h] += __shfl_xor_sync(0xffffffffu, dsum[s][h], 2);
        }
    }

    // write Y fp16 [b][q][ci]
#pragma unroll
    for (int s = 0; s < 2; s++) {
        float rlo = 1.f / dsum[s][0], rhi = 1.f / dsum[s][1];
        size_t olo = ((size_t)b * NPOS + q0 + w * 32 + s * 16 + g) * CI;
        size_t ohi = olo + (size_t)8 * CI;
#pragma unroll
        for (int ct = 0; ct < 16; ct++) {
            int ch = ct * 8 + 2 * t;
            *reinterpret_cast<uint32_t*>(&Yg[olo + ch]) = packh2(Yacc[s][ct][0] * rlo, Yacc[s][ct][1] * rlo);
            *reinterpret_cast<uint32_t*>(&Yg[ohi + ch]) = packh2(Yacc[s][ct][2] * rhi, Yacc[s][ct][3] * rhi);
        }
    }
}

// ============================================================================
// Kernel 3: wy = Ww @ y + bw  -> wyg [b][256][n], plus per-block BN partials.
// Block: 64 n rows, 256 threads (8 warps): (mw = w&3) m16 tile, (ow = w>>2)
// 128-oc half (16 n8 tiles).
// ============================================================================
__global__ void __launch_bounds__(256)
wproj_kernel(const float* __restrict__ Ww, const float* __restrict__ bw)
{
    __shared__ __half Ys[64 * 136];
    __shared__ __half Ws2[256 * 40];
    __shared__ float  ps[4][256];
    __shared__ float  pq[4][256];

    const int tid  = threadIdx.x;
    const int w    = tid >> 5;
    const int lane = tid & 31;
    const int g = lane >> 2, t = lane & 3;
    const int b  = blockIdx.y;
    const int n0 = blockIdx.x * 64;
    const int mw = w & 3;
    const int ow = w >> 2;

    {   // Y tile [64][128]
        int row = tid >> 2, off = (tid & 3) * 32;
        const uint4* src = reinterpret_cast<const uint4*>(&Yg[((size_t)b * NPOS + n0 + row) * CI + off]);
        uint4* dst = reinterpret_cast<uint4*>(&Ys[row * 136 + off]);
#pragma unroll
        for (int i = 0; i < 4; i++) dst[i] = src[i];
    }

    float acc[16][4];
#pragma unroll
    for (int i = 0; i < 16; i++) { acc[i][0]=acc[i][1]=acc[i][2]=acc[i][3]=0.f; }

    for (int kc = 0; kc < CI; kc += 32) {
        __syncthreads();
#pragma unroll
        for (int it = 0; it < 16; it++) {
            int p = tid + 256 * it;
            int oc = p >> 4, c2 = p & 15;
            float2 v = *reinterpret_cast<const float2*>(&Ww[oc * CI + kc + 2 * c2]);
            *reinterpret_cast<uint32_t*>(&Ws2[oc * 40 + 2 * c2]) = packh2(v.x, v.y);
        }
        __syncthreads();
#pragma unroll
        for (int ks = 0; ks < 2; ks++) {
            uint32_t a[4];
            int base = (mw * 16 + g) * 136 + kc + ks * 16 + 2 * t;
            a[0] = *reinterpret_cast<const uint32_t*>(&Ys[base]);
            a[1] = *reinterpret_cast<const uint32_t*>(&Ys[base + 8 * 136]);
            a[2] = *reinterpret_cast<const uint32_t*>(&Ys[base + 8]);
            a[3] = *reinterpret_cast<const uint32_t*>(&Ys[base + 8 * 136 + 8]);
#pragma unroll
            for (int i = 0; i < 16; i++) {
                int ocr = (ow * 16 + i) * 8 + g;
                uint32_t b0 = *reinterpret_cast<const uint32_t*>(&Ws2[ocr * 40 + ks * 16 + 2 * t]);
                uint32_t b1 = *reinterpret_cast<const uint32_t*>(&Ws2[ocr * 40 + ks * 16 + 2 * t + 8]);
                mma16816(acc[i], a, b0, b1);
            }
        }
    }
    // epilogue: bias, store wy fp32, per-warp BN partials (deterministic)
    const int row_lo = n0 + mw * 16 + g;
    const int row_hi = row_lo + 8;
#pragma unroll
    for (int i = 0; i < 16; i++) {
        int oc0 = ow * 128 + i * 8 + 2 * t;
        float bw0 = bw[oc0], bw1 = bw[oc0 + 1];
        float v0 = acc[i][0] + bw0, v1 = acc[i][1] + bw1;
        float v2 = acc[i][2] + bw0, v3 = acc[i][3] + bw1;
        size_t base = ((size_t)b * CH + oc0) * NPOS;
        wyg[base + row_lo]        = v0;
        wyg[base + NPOS + row_lo] = v1;
        wyg[base + row_hi]        = v2;
        wyg[base + NPOS + row_hi] = v3;
        float s0 = v0 + v2, s1 = v1 + v3;
        float q0s = v0 * v0 + v2 * v2, q1s = v1 * v1 + v3 * v3;
#pragma unroll
        for (int m = 4; m <= 16; m <<= 1) {
            s0  += __shfl_xor_sync(0xffffffffu, s0, m);
            s1  += __shfl_xor_sync(0xffffffffu, s1, m);
            q0s += __shfl_xor_sync(0xffffffffu, q0s, m);
            q1s += __shfl_xor_sync(0xffffffffu, q1s, m);
        }
        if (lane < 4) {  // g==0, t==lane
            int oc = ow * 128 + i * 8 + 2 * lane;
            ps[mw][oc] = s0;  ps[mw][oc + 1] = s1;
            pq[mw][oc] = q0s; pq[mw][oc + 1] = q1s;
        }
    }
    __syncthreads();
    {   // combine across m-tiles, store block partials
        float s = ps[0][tid] + ps[1][tid] + ps[2][tid] + ps[3][tid];
        float q = pq[0][tid] + pq[1][tid] + pq[2][tid] + pq[3][tid];
        int blk = blockIdx.y * NBLK + blockIdx.x;
        psum_g[blk * CH + tid] = s;
        psq_g [blk * CH + tid] = q;
    }
}

// ============================================================================
// Kernel 4: BN stats -> scale/shift. 1024 threads: 4 chunks x 256 channels,
// fixed-order tree combine (deterministic).
// ============================================================================
__global__ void __launch_bounds__(1024)
bnstats_kernel(const float* __restrict__ gamma,
               const float* __restrict__ beta)
{
    __shared__ float ss[4][CH];
    __shared__ float qq[4][CH];
    const int c     = threadIdx.x & 255;
    const int chunk = threadIdx.x >> 8;   // 0..3, 64 blocks each
    float s = 0.f, q = 0.f;
#pragma unroll 8
    for (int i = 0; i < 64; i++) {
        int blk = chunk * 64 + i;
        s += psum_g[blk * CH + c];
        q += psq_g [blk * CH + c];
    }
    ss[chunk][c] = s; qq[chunk][c] = q;
    __syncthreads();
    if (threadIdx.x < CH) {
        float st = (ss[0][c] + ss[1][c]) + (ss[2][c] + ss[3][c]);
        float qt = (qq[0][c] + qq[1][c]) + (qq[2][c] + qq[3][c]);
        const float inv = 1.f / (float)(BATCH * NPOS);
        float mean = st * inv;
        float var  = qt * inv - mean * mean;
        float sc = gamma[c] * rsqrtf(var + 1e-5f);
        scale_g[c] = sc;
        shift_g[c] = beta[c] - mean * sc;
    }
}

// ============================================================================
// Kernel 5: out = wy * scale + shift + x  (vectorized)
// ============================================================================
__global__ void __launch_bounds__(256)
final_kernel(const float* __restrict__ x, float* __restrict__ out)
{
    size_t e = ((size_t)blockIdx.x * 256 + threadIdx.x) * 4;
    int c = (int)((e >> 13) & 255);
    float4 wv = *reinterpret_cast<const float4*>(&wyg[e]);
    float4 xv = *reinterpret_cast<const float4*>(&x[e]);
    float sc = scale_g[c], sh = shift_g[c];
    float4 o;
    o.x = wv.x * sc + sh + xv.x;
    o.y = wv.y * sc + sh + xv.y;
    o.z = wv.z * sc + sh + xv.z;
    o.w = wv.w * sc + sh + xv.w;
    *reinterpret_cast<float4*>(&out[e]) = o;
}

// ============================================================================
extern "C" void kernel_launch(void* const* d_in, const int* in_sizes, int n_in,
                              void* d_out, int out_size)
{
    const float* x     = (const float*)d_in[0];
    const float* Wt    = (const float*)d_in[1];
    const float* bt    = (const float*)d_in[2];
    const float* Wp    = (const float*)d_in[3];
    const float* bp    = (const float*)d_in[4];
    const float* Wg    = (const float*)d_in[5];
    const float* bg    = (const float*)d_in[6];
    const float* Ww    = (const float*)d_in[7];
    const float* bw    = (const float*)d_in[8];
    const float* gamma = (const float*)d_in[9];
    const float* beta  = (const float*)d_in[10];
    float* out = (float*)d_out;

    // Unconditional every call (no static guards — harness determinism rule).
    cudaFuncSetAttribute(attn_kernel,
                         cudaFuncAttributeMaxDynamicSharedMemorySize,
                         ATTN_SMEM_BYTES);

    proj_kernel<<<dim3(NBLK, BATCH), 256>>>(x, Wt, bt, Wp, bp, Wg, bg);
    attn_kernel<<<dim3(NPOS / 128, BATCH), 128, ATTN_SMEM_BYTES>>>();
    wproj_kernel<<<dim3(NBLK, BATCH), 256>>>(Ww, bw);
    bnstats_kernel<<<1, 1024>>>(gamma, beta);
    final_kernel<<<(BATCH * CH * NPOS) / (256 * 4), 256>>>(x, out);
}

// round 14
// speedup vs baseline: 1.7954x; 1.5438x over previous
#include <cuda_runtime.h>
#include <cuda_fp16.h>
#include <cstdint>

#define BATCH 2
#define CH    256
#define CI    128
#define NPOS  8192
#define NBLK  128   // NPOS / 64

// attention smem geometry (in __half units)
#define QS_H   (128 * 136)           // persistent Q tile [q][ci]
#define KS_H   (64 * 136)            // K tile [kv][ci], stride 136
#define VS_H   (128 * 72)            // V tile [ci][kv], stride 72
#define STAGE_H (KS_H + VS_H)        // one pipeline stage
#define ATTN_SMEM_BYTES ((QS_H + 2 * STAGE_H) * 2)   // 106496 B

// ---------------- scratch (static __device__, no allocations) ----------------
__device__ __half Qg [(size_t)BATCH*NPOS*CI];   // [b][n][ci]
__device__ __half Kg2[(size_t)BATCH*NPOS*CI];   // [b][n][ci]
__device__ __half Vg [(size_t)BATCH*CI*NPOS];   // [b][ci][n]  (transposed)
__device__ __half Yg [(size_t)BATCH*NPOS*CI];   // [b][n][ci]
__device__ float  wyg[(size_t)BATCH*CH*NPOS];   // [b][c][n]
__device__ float  psum_g[CH*BATCH*NBLK];        // [c][blk]  (transposed for bnstats)
__device__ float  psq_g [CH*BATCH*NBLK];
__device__ float  scale_g[CH];
__device__ float  shift_g[CH];

// ---------------- helpers ----------------
__device__ __forceinline__ uint32_t packh2(float a, float b) {
    __half2 h = __floats2half2_rn(a, b);
    return *reinterpret_cast<uint32_t*>(&h);
}
__device__ __forceinline__ void mma16816(float* c, const uint32_t* a,
                                         uint32_t b0, uint32_t b1) {
    asm volatile(
        "mma.sync.aligned.m16n8k16.row.col.f32.f16.f16.f32 "
        "{%0,%1,%2,%3},{%4,%5,%6,%7},{%8,%9},{%0,%1,%2,%3};\n"
        : "+f"(c[0]), "+f"(c[1]), "+f"(c[2]), "+f"(c[3])
        : "r"(a[0]), "r"(a[1]), "r"(a[2]), "r"(a[3]), "r"(b0), "r"(b1));
}
__device__ __forceinline__ void ldsm4(uint32_t* r, uint32_t addr) {
    asm volatile(
        "ldmatrix.sync.aligned.m8n8.x4.shared.b16 {%0,%1,%2,%3}, [%4];\n"
        : "=r"(r[0]), "=r"(r[1]), "=r"(r[2]), "=r"(r[3]) : "r"(addr));
}
__device__ __forceinline__ void cp16(uint32_t dst_s, const void* src_g) {
    asm volatile("cp.async.cg.shared.global [%0], [%1], 16;\n"
                 :: "r"(dst_s), "l"(src_g));
}
__device__ __forceinline__ void cp_commit() { asm volatile("cp.async.commit_group;\n"); }
__device__ __forceinline__ void cp_wait0()  { asm volatile("cp.async.wait_group 0;\n"); }
__device__ __forceinline__ void cp_wait1()  { asm volatile("cp.async.wait_group 1;\n"); }
__device__ __forceinline__ void cp_wait2()  { asm volatile("cp.async.wait_group 2;\n"); }

// ============================================================================
// Kernel 1: fused theta/phi/g projections.
// ============================================================================
__global__ void __launch_bounds__(256)
proj_kernel(const float* __restrict__ x,
            const float* __restrict__ Wt, const float* __restrict__ bt,
            const float* __restrict__ Wp, const float* __restrict__ bp,
            const float* __restrict__ Wg, const float* __restrict__ bg)
{
    __shared__ __half Ws[384 * 40];
    __shared__ __half Xs[64 * 40];

    const int tid  = threadIdx.x;
    const int w    = tid >> 5;
    const int lane = tid & 31;
    const int g = lane >> 2, t = lane & 3;
    const int b  = blockIdx.y;
    const int n0 = blockIdx.x * 64;
    const int mw = w & 3;
    const int ow = w >> 2;

    float acc[24][4];
#pragma unroll
    for (int i = 0; i < 24; i++) { acc[i][0]=acc[i][1]=acc[i][2]=acc[i][3]=0.f; }

    for (int kc = 0; kc < CH; kc += 32) {
        __syncthreads();
#pragma unroll
        for (int it = 0; it < 24; it++) {
            int p = tid + 256 * it;
            int row = p >> 4, c2 = p & 15;
            const float* src; int r = row;
            if (row < 128)      { src = Wt; }
            else if (row < 256) { src = Wp; r = row - 128; }
            else                { src = Wg; r = row - 256; }
            float2 v = *reinterpret_cast<const float2*>(&src[r * CH + kc + 2 * c2]);
            *reinterpret_cast<uint32_t*>(&Ws[row * 40 + 2 * c2]) = packh2(v.x, v.y);
        }
#pragma unroll
        for (int it = 0; it < 4; it++) {
            int p = tid + 256 * it;
            int cl = p >> 5, j2 = p & 31;
            float2 v = *reinterpret_cast<const float2*>(
                &x[((size_t)(b * CH + kc + cl)) * NPOS + n0 + 2 * j2]);
            Xs[(2 * j2)     * 40 + cl] = __float2half_rn(v.x);
            Xs[(2 * j2 + 1) * 40 + cl] = __float2half_rn(v.y);
        }
        __syncthreads();
#pragma unroll
        for (int ks = 0; ks < 2; ks++) {
            uint32_t a[4];
            int base = (mw * 16 + g) * 40 + ks * 16 + 2 * t;
            a[0] = *reinterpret_cast<const uint32_t*>(&Xs[base]);
            a[1] = *reinterpret_cast<const uint32_t*>(&Xs[base + 8 * 40]);
            a[2] = *reinterpret_cast<const uint32_t*>(&Xs[base + 8]);
            a[3] = *reinterpret_cast<const uint32_t*>(&Xs[base + 8 * 40 + 8]);
#pragma unroll
            for (int i = 0; i < 24; i++) {
                int ocr = (ow * 24 + i) * 8 + g;
                uint32_t b0 = *reinterpret_cast<const uint32_t*>(&Ws[ocr * 40 + ks * 16 + 2 * t]);
                uint32_t b1 = *reinterpret_cast<const uint32_t*>(&Ws[ocr * 40 + ks * 16 + 2 * t + 8]);
                mma16816(acc[i], a, b0, b1);
            }
        }
    }
    const int row_lo = n0 + mw * 16 + g;
    const int row_hi = row_lo + 8;
#pragma unroll
    for (int i = 0; i < 24; i++) {
        int col0 = ow * 192 + i * 8 + 2 * t;
        int arr  = col0 >> 7;
        int ch   = col0 & 127;
        const float* bias = (arr == 0) ? bt : (arr == 1) ? bp : bg;
        float b0v = bias[ch], b1v = bias[ch + 1];
        float v0 = acc[i][0] + b0v, v1 = acc[i][1] + b1v;
        float v2 = acc[i][2] + b0v, v3 = acc[i][3] + b1v;
        if (arr == 2) {
            size_t base = ((size_t)b * CI + ch) * NPOS;
            Vg[base + row_lo]        = __float2half_rn(v0);
            Vg[base + NPOS + row_lo] = __float2half_rn(v1);
            Vg[base + row_hi]        = __float2half_rn(v2);
            Vg[base + NPOS + row_hi] = __float2half_rn(v3);
        } else {
            __half* dst = (arr == 0) ? Qg : Kg2;
            *reinterpret_cast<uint32_t*>(&dst[((size_t)b * NPOS + row_lo) * CI + ch]) = packh2(v0, v1);
            *reinterpret_cast<uint32_t*>(&dst[((size_t)b * NPOS + row_hi) * CI + ch]) = packh2(v2, v3);
        }
    }
}

// ============================================================================
// Kernel 2: flash attention, kv-split warp pairs.
// 256 threads (8 warps). Pair p = w>>1 owns q rows [q0+32p, +32); half h = w&1
// owns kv columns [32h, 32h+32) of each 64-wide KV tile. 2 warps/SMSP.
// All frags via ldmatrix.x4; Q persistent in smem; K/V double-buffered
// cp.async. Partial Y/dsum combined through smem at the end (no-max softmax
// sums add linearly).
// ============================================================================
__global__ void __launch_bounds__(256)
attn_kernel()
{
    extern __shared__ __half sm[];   // [Qs 128x136][stage0 K|V][stage1 K|V]

    const int tid  = threadIdx.x;
    const int w    = tid >> 5;
    const int lane = tid & 31;
    const int g = lane >> 2, t = lane & 3;
    const int pair = w >> 1, h = w & 1;
    const int b  = blockIdx.y;
    const int q0 = blockIdx.x * 128;
    const size_t bN = (size_t)b * NPOS;

    const uint32_t sm_s = (uint32_t)__cvta_generic_to_shared(sm);

    // ldmatrix per-thread row offsets (bytes)
    const int mrow = lane >> 3, r8 = lane & 7;
    const uint32_t offA = (uint32_t)(((mrow & 1) * 8 + r8) * 272 + (mrow >> 1) * 16);
    const uint32_t offB = (uint32_t)(((mrow >> 1) * 8 + r8) * 272 + (mrow & 1) * 16);
    const uint32_t offV = (uint32_t)(((mrow >> 1) * 8 + r8) * 144 + (mrow & 1) * 16);

    // ---- async-load Q tile (group 0): 128 rows x 16 chunks of 16B ----
#pragma unroll
    for (int i = 0; i < 8; i++) {
        int s_ = tid + 256 * i;
        int row = s_ >> 4, c = s_ & 15;
        cp16(sm_s + row * 272 + c * 16, &Qg[(bN + q0 + row) * CI + c * 8]);
    }
    cp_commit();

    // ---- prime K/V stages (groups 1,2) ----
#pragma unroll
    for (int pre = 0; pre < 2; pre++) {
        uint32_t kb = sm_s + (QS_H + pre * STAGE_H) * 2;
        uint32_t vb = kb + KS_H * 2;
#pragma unroll
        for (int i = 0; i < 4; i++) {        // K: 64 rows x 16 chunks
            int s_ = tid + 256 * i;
            int row = s_ >> 4, c = s_ & 15;
            cp16(kb + row * 272 + c * 16, &Kg2[(bN + pre * 64 + row) * CI + c * 8]);
        }
#pragma unroll
        for (int i = 0; i < 4; i++) {        // V: 128 rows x 8 chunks
            int s_ = tid + 256 * i;
            int ci = s_ >> 3, c = s_ & 7;
            cp16(vb + ci * 144 + c * 16, &Vg[((size_t)b * CI + ci) * NPOS + pre * 64 + c * 8]);
        }
        cp_commit();
    }
    cp_wait2();          // Q resident
    __syncthreads();

    float Yacc[2][16][4];
#pragma unroll
    for (int s = 0; s < 2; s++)
#pragma unroll
        for (int i = 0; i < 16; i++) { Yacc[s][i][0]=Yacc[s][i][1]=Yacc[s][i][2]=Yacc[s][i][3]=0.f; }
    float dsum[2][2] = {{0.f, 0.f}, {0.f, 0.f}};

    const uint32_t qa_base = sm_s + pair * 32 * 272 + offA;   // + sub*4352 + kc*32

    for (int kt = 0; kt < NBLK; kt++) {
        uint32_t kstage = sm_s + (QS_H + (kt & 1) * STAGE_H) * 2;
        uint32_t vstage = kstage + KS_H * 2;
        const uint32_t kb_base = kstage + h * 32 * 272 + offB;       // + jj*4352 + kc*32
        const uint32_t vb_base = vstage + (h * 32) * 2 + offV;       // + j*32 + ctg*2304

        if (kt < NBLK - 1) cp_wait1(); else cp_wait0();
        __syncthreads();

        // ---- S = Q K^T over this warp's kv half (n32) ----
        float S2[2][4][4];
#pragma unroll
        for (int s = 0; s < 2; s++)
#pragma unroll
            for (int nb = 0; nb < 4; nb++) { S2[s][nb][0]=S2[s][nb][1]=S2[s][nb][2]=S2[s][nb][3]=0.f; }
#pragma unroll
        for (int kc = 0; kc < 8; kc++) {
            uint32_t A0[4], A1[4], B0[4], B1[4];
            ldsm4(A0, qa_base + kc * 32);
            ldsm4(A1, qa_base + 4352 + kc * 32);
            ldsm4(B0, kb_base + kc * 32);
            ldsm4(B1, kb_base + 4352 + kc * 32);
            mma16816(S2[0][0], A0, B0[0], B0[1]);
            mma16816(S2[0][1], A0, B0[2], B0[3]);
            mma16816(S2[0][2], A0, B1[0], B1[1]);
            mma16816(S2[0][3], A0, B1[2], B1[3]);
            mma16816(S2[1][0], A1, B0[0], B0[1]);
            mma16816(S2[1][1], A1, B0[2], B0[3]);
            mma16816(S2[1][2], A1, B1[0], B1[1]);
            mma16816(S2[1][3], A1, B1[2], B1[3]);
        }

        // ---- P = exp(S); pack into PV A-frags; accumulate row sums ----
        uint32_t Ap[2][2][4];
#pragma unroll
        for (int s = 0; s < 2; s++) {
#pragma unroll
            for (int nb = 0; nb < 4; nb++) {
                float e0 = __expf(S2[s][nb][0]), e1 = __expf(S2[s][nb][1]);
                float e2 = __expf(S2[s][nb][2]), e3 = __expf(S2[s][nb][3]);
                dsum[s][0] += e0 + e1;
                dsum[s][1] += e2 + e3;
                int j = nb >> 1;
                if ((nb & 1) == 0) {
                    Ap[s][j][0] = packh2(e0, e1);
                    Ap[s][j][1] = packh2(e2, e3);
                } else {
                    Ap[s][j][2] = packh2(e0, e1);
                    Ap[s][j][3] = packh2(e2, e3);
                }
            }
        }

        // ---- Y += P V over this warp's kv half (k32) ----
#pragma unroll
        for (int j = 0; j < 2; j++) {
#pragma unroll
            for (int ctg = 0; ctg < 8; ctg++) {
                uint32_t Bv[4];
                ldsm4(Bv, vb_base + j * 32 + ctg * 2304);
                mma16816(Yacc[0][2 * ctg],     Ap[0][j], Bv[0], Bv[1]);
                mma16816(Yacc[0][2 * ctg + 1], Ap[0][j], Bv[2], Bv[3]);
                mma16816(Yacc[1][2 * ctg],     Ap[1][j], Bv[0], Bv[1]);
                mma16816(Yacc[1][2 * ctg + 1], Ap[1][j], Bv[2], Bv[3]);
            }
        }
        __syncthreads();

        if (kt + 2 < NBLK) {   // refill the stage just freed
            uint32_t kb = sm_s + (QS_H + (kt & 1) * STAGE_H) * 2;
            uint32_t vb = kb + KS_H * 2;
#pragma unroll
            for (int i = 0; i < 4; i++) {    // K: 64 rows x 16 chunks
                int s_ = tid + 256 * i;
                int row = s_ >> 4, c = s_ & 15;
                cp16(kb + row * 272 + c * 16, &Kg2[(bN + (kt + 2) * 64 + row) * CI + c * 8]);
            }
#pragma unroll
            for (int i = 0; i < 4; i++) {    // V: 128 rows x 8 chunks
                int s_ = tid + 256 * i;
                int ci = s_ >> 3, c = s_ & 7;
                cp16(vb + ci * 144 + c * 16, &Vg[((size_t)b * CI + ci) * NPOS + (kt + 2) * 64 + c * 8]);
            }
            cp_commit();
        }
    }

    // ---- intra-warp row sums over t ----
#pragma unroll
    for (int s = 0; s < 2; s++)
#pragma unroll
        for (int hl = 0; hl < 2; hl++) {
            dsum[s][hl] += __shfl_xor_sync(0xffffffffu, dsum[s][hl], 1);
            dsum[s][hl] += __shfl_xor_sync(0xffffffffu, dsum[s][hl], 2);
        }

    // ---- combine kv halves through smem (stages no longer needed) ----
    float* smf = reinterpret_cast<float*>(sm);
    if (h == 1) {
#pragma unroll
        for (int s = 0; s < 2; s++)
#pragma unroll
            for (int ct = 0; ct < 16; ct++)
#pragma unroll
                for (int i = 0; i < 4; i++)
                    smf[pair * 4096 + ((s * 16 + ct) * 4 + i) * 32 + lane] = Yacc[s][ct][i];
        if (t == 0) {
#pragma unroll
            for (int s = 0; s < 2; s++) {
                smf[16384 + pair * 32 + s * 16 + g]     = dsum[s][0];
                smf[16384 + pair * 32 + s * 16 + 8 + g] = dsum[s][1];
            }
        }
    }
    __syncthreads();
    if (h == 0) {
#pragma unroll
        for (int s = 0; s < 2; s++) {
            float dl = dsum[s][0] + smf[16384 + pair * 32 + s * 16 + g];
            float dh = dsum[s][1] + smf[16384 + pair * 32 + s * 16 + 8 + g];
            float rlo = 1.f / dl, rhi = 1.f / dh;
            size_t olo = (bN + q0 + pair * 32 + s * 16 + g) * CI;
            size_t ohi = olo + (size_t)8 * CI;
#pragma unroll
            for (int ct = 0; ct < 16; ct++) {
                int base = pair * 4096 + ((s * 16 + ct) * 4) * 32 + lane;
                float y0 = Yacc[s][ct][0] + smf[base];
                float y1 = Yacc[s][ct][1] + smf[base + 32];
                float y2 = Yacc[s][ct][2] + smf[base + 64];
                float y3 = Yacc[s][ct][3] + smf[base + 96];
                int ch = ct * 8 + 2 * t;
                *reinterpret_cast<uint32_t*>(&Yg[olo + ch]) = packh2(y0 * rlo, y1 * rlo);
                *reinterpret_cast<uint32_t*>(&Yg[ohi + ch]) = packh2(y2 * rhi, y3 * rhi);
            }
        }
    }
}

// ============================================================================
// Kernel 3: wy = Ww @ y + bw -> wyg, plus per-block BN partials
// (partials stored transposed [c][blk] for coalesced bnstats).
// ============================================================================
__global__ void __launch_bounds__(256)
wproj_kernel(const float* __restrict__ Ww, const float* __restrict__ bw)
{
    __shared__ __half Ys[64 * 136];
    __shared__ __half Ws2[256 * 40];
    __shared__ float  ps[4][256];
    __shared__ float  pq[4][256];

    const int tid  = threadIdx.x;
    const int w    = tid >> 5;
    const int lane = tid & 31;
    const int g = lane >> 2, t = lane & 3;
    const int b  = blockIdx.y;
    const int n0 = blockIdx.x * 64;
    const int mw = w & 3;
    const int ow = w >> 2;

    {
        int row = tid >> 2, off = (tid & 3) * 32;
        const uint4* src = reinterpret_cast<const uint4*>(&Yg[((size_t)b * NPOS + n0 + row) * CI + off]);
        uint4* dst = reinterpret_cast<uint4*>(&Ys[row * 136 + off]);
#pragma unroll
        for (int i = 0; i < 4; i++) dst[i] = src[i];
    }

    float acc[16][4];
#pragma unroll
    for (int i = 0; i < 16; i++) { acc[i][0]=acc[i][1]=acc[i][2]=acc[i][3]=0.f; }

    for (int kc = 0; kc < CI; kc += 32) {
        __syncthreads();
#pragma unroll
        for (int it = 0; it < 16; it++) {
            int p = tid + 256 * it;
            int oc = p >> 4, c2 = p & 15;
            float2 v = *reinterpret_cast<const float2*>(&Ww[oc * CI + kc + 2 * c2]);
            *reinterpret_cast<uint32_t*>(&Ws2[oc * 40 + 2 * c2]) = packh2(v.x, v.y);
        }
        __syncthreads();
#pragma unroll
        for (int ks = 0; ks < 2; ks++) {
            uint32_t a[4];
            int base = (mw * 16 + g) * 136 + kc + ks * 16 + 2 * t;
            a[0] = *reinterpret_cast<const uint32_t*>(&Ys[base]);
            a[1] = *reinterpret_cast<const uint32_t*>(&Ys[base + 8 * 136]);
            a[2] = *reinterpret_cast<const uint32_t*>(&Ys[base + 8]);
            a[3] = *reinterpret_cast<const uint32_t*>(&Ys[base + 8 * 136 + 8]);
#pragma unroll
            for (int i = 0; i < 16; i++) {
                int ocr = (ow * 16 + i) * 8 + g;
                uint32_t b0 = *reinterpret_cast<const uint32_t*>(&Ws2[ocr * 40 + ks * 16 + 2 * t]);
                uint32_t b1 = *reinterpret_cast<const uint32_t*>(&Ws2[ocr * 40 + ks * 16 + 2 * t + 8]);
                mma16816(acc[i], a, b0, b1);
            }
        }
    }
    const int row_lo = n0 + mw * 16 + g;
    const int row_hi = row_lo + 8;
#pragma unroll
    for (int i = 0; i < 16; i++) {
        int oc0 = ow * 128 + i * 8 + 2 * t;
        float bw0 = bw[oc0], bw1 = bw[oc0 + 1];
        float v0 = acc[i][0] + bw0, v1 = acc[i][1] + bw1;
        float v2 = acc[i][2] + bw0, v3 = acc[i][3] + bw1;
        size_t base = ((size_t)b * CH + oc0) * NPOS;
        wyg[base + row_lo]        = v0;
        wyg[base + NPOS + row_lo] = v1;
        wyg[base + row_hi]        = v2;
        wyg[base + NPOS + row_hi] = v3;
        float s0 = v0 + v2, s1 = v1 + v3;
        float q0s = v0 * v0 + v2 * v2, q1s = v1 * v1 + v3 * v3;
#pragma unroll
        for (int m = 4; m <= 16; m <<= 1) {
            s0  += __shfl_xor_sync(0xffffffffu, s0, m);
            s1  += __shfl_xor_sync(0xffffffffu, s1, m);
            q0s += __shfl_xor_sync(0xffffffffu, q0s, m);
            q1s += __shfl_xor_sync(0xffffffffu, q1s, m);
        }
        if (lane < 4) {
            int oc = ow * 128 + i * 8 + 2 * lane;
            ps[mw][oc] = s0;  ps[mw][oc + 1] = s1;
            pq[mw][oc] = q0s; pq[mw][oc + 1] = q1s;
        }
    }
    __syncthreads();
    {
        float s = ps[0][tid] + ps[1][tid] + ps[2][tid] + ps[3][tid];
        float q = pq[0][tid] + pq[1][tid] + pq[2][tid] + pq[3][tid];
        int blk = blockIdx.y * NBLK + blockIdx.x;
        psum_g[tid * (BATCH * NBLK) + blk] = s;   // [c][blk]
        psq_g [tid * (BATCH * NBLK) + blk] = q;
    }
}

// ============================================================================
// Kernel 4: BN stats. One block per channel; coalesced reads; fixed-order tree.
// ============================================================================
__global__ void __launch_bounds__(256)
bnstats_kernel(const float* __restrict__ gamma,
               const float* __restrict__ beta)
{
    __shared__ float ss[256];
    __shared__ float qq[256];
    const int c = blockIdx.x, tid = threadIdx.x;
    ss[tid] = psum_g[c * 256 + tid];
    qq[tid] = psq_g [c * 256 + tid];
    __syncthreads();
#pragma unroll
    for (int m = 128; m > 0; m >>= 1) {
        if (tid < m) { ss[tid] += ss[tid + m]; qq[tid] += qq[tid + m]; }
        __syncthreads();
    }
    if (tid == 0) {
        const float inv = 1.f / (float)(BATCH * NPOS);
        float mean = ss[0] * inv;
        float var  = qq[0] * inv - mean * mean;
        float sc = gamma[c] * rsqrtf(var + 1e-5f);
        scale_g[c] = sc;
        shift_g[c] = beta[c] - mean * sc;
    }
}

// ============================================================================
// Kernel 5: out = wy * scale + shift + x
// ============================================================================
__global__ void __launch_bounds__(256)
final_kernel(const float* __restrict__ x, float* __restrict__ out)
{
    size_t e = ((size_t)blockIdx.x * 256 + threadIdx.x) * 4;
    int c = (int)((e >> 13) & 255);
    float4 wv = *reinterpret_cast<const float4*>(&wyg[e]);
    float4 xv = *reinterpret_cast<const float4*>(&x[e]);
    float sc = scale_g[c], sh = shift_g[c];
    float4 o;
    o.x = wv.x * sc + sh + xv.x;
    o.y = wv.y * sc + sh + xv.y;
    o.z = wv.z * sc + sh + xv.z;
    o.w = wv.w * sc + sh + xv.w;
    *reinterpret_cast<float4*>(&out[e]) = o;
}

// ============================================================================
extern "C" void kernel_launch(void* const* d_in, const int* in_sizes, int n_in,
                              void* d_out, int out_size)
{
    const float* x     = (const float*)d_in[0];
    const float* Wt    = (const float*)d_in[1];
    const float* bt    = (const float*)d_in[2];
    const float* Wp    = (const float*)d_in[3];
    const float* bp    = (const float*)d_in[4];
    const float* Wg    = (const float*)d_in[5];
    const float* bg    = (const float*)d_in[6];
    const float* Ww    = (const float*)d_in[7];
    const float* bw    = (const float*)d_in[8];
    const float* gamma = (const float*)d_in[9];
    const float* beta  = (const float*)d_in[10];
    float* out = (float*)d_out;

    cudaFuncSetAttribute(attn_kernel,
                         cudaFuncAttributeMaxDynamicSharedMemorySize,
                         ATTN_SMEM_BYTES);

    proj_kernel<<<dim3(NBLK, BATCH), 256>>>(x, Wt, bt, Wp, bp, Wg, bg);
    attn_kernel<<<dim3(NPOS / 128, BATCH), 256, ATTN_SMEM_BYTES>>>();
    wproj_kernel<<<dim3(NBLK, BATCH), 256>>>(Ww, bw);
    bnstats_kernel<<<CH, 256>>>(gamma, beta);
    final_kernel<<<(BATCH * CH * NPOS) / (256 * 4), 256>>>(x, out);
}

// round 17
// speedup vs baseline: 1.8077x; 1.0069x over previous
#include <cuda_runtime.h>
#include <cuda_fp16.h>
#include <cstdint>

#define BATCH 2
#define CH    256
#define CI    128
#define NPOS  8192
#define NBLK  128   // NPOS / 64

// attention smem geometry (in __half units)
#define QS_H   (128 * 136)           // persistent Q tile [q][ci]
#define KS_H   (64 * 136)            // K tile [kv][ci], stride 136
#define VS_H   (128 * 72)            // V tile [ci][kv], stride 72
#define STAGE_H (KS_H + VS_H)        // one pipeline stage
#define NSTAGE 3
#define ATTN_SMEM_BYTES ((QS_H + NSTAGE * STAGE_H) * 2)   // 142336 B

// ---------------- scratch (static __device__, no allocations) ----------------
__device__ __half Qg [(size_t)BATCH*NPOS*CI];   // [b][n][ci]
__device__ __half Kg2[(size_t)BATCH*NPOS*CI];   // [b][n][ci]
__device__ __half Vg [(size_t)BATCH*CI*NPOS];   // [b][ci][n]  (transposed)
__device__ __half Yg [(size_t)BATCH*NPOS*CI];   // [b][n][ci]
__device__ float  wyg[(size_t)BATCH*CH*NPOS];   // [b][c][n]
__device__ float  psum_g[CH*BATCH*NBLK];        // [c][blk]  (transposed for bnstats)
__device__ float  psq_g [CH*BATCH*NBLK];
__device__ float  scale_g[CH];
__device__ float  shift_g[CH];

// ---------------- helpers ----------------
__device__ __forceinline__ uint32_t packh2(float a, float b) {
    __half2 h = __floats2half2_rn(a, b);
    return *reinterpret_cast<uint32_t*>(&h);
}
__device__ __forceinline__ void mma16816(float* c, const uint32_t* a,
                                         uint32_t b0, uint32_t b1) {
    asm volatile(
        "mma.sync.aligned.m16n8k16.row.col.f32.f16.f16.f32 "
        "{%0,%1,%2,%3},{%4,%5,%6,%7},{%8,%9},{%0,%1,%2,%3};\n"
        : "+f"(c[0]), "+f"(c[1]), "+f"(c[2]), "+f"(c[3])
        : "r"(a[0]), "r"(a[1]), "r"(a[2]), "r"(a[3]), "r"(b0), "r"(b1));
}
__device__ __forceinline__ void ldsm4(uint32_t* r, uint32_t addr) {
    asm volatile(
        "ldmatrix.sync.aligned.m8n8.x4.shared.b16 {%0,%1,%2,%3}, [%4];\n"
        : "=r"(r[0]), "=r"(r[1]), "=r"(r[2]), "=r"(r[3]) : "r"(addr));
}
__device__ __forceinline__ void cp16(uint32_t dst_s, const void* src_g) {
    asm volatile("cp.async.cg.shared.global [%0], [%1], 16;\n"
                 :: "r"(dst_s), "l"(src_g));
}
__device__ __forceinline__ void cp_commit() { asm volatile("cp.async.commit_group;\n"); }
__device__ __forceinline__ void cp_wait0()  { asm volatile("cp.async.wait_group 0;\n"); }
__device__ __forceinline__ void cp_wait1()  { asm volatile("cp.async.wait_group 1;\n"); }
__device__ __forceinline__ void cp_wait2()  { asm volatile("cp.async.wait_group 2;\n"); }

// ============================================================================
// Kernel 1: fused theta/phi/g projections.
// ============================================================================
__global__ void __launch_bounds__(256)
proj_kernel(const float* __restrict__ x,
            const float* __restrict__ Wt, const float* __restrict__ bt,
            const float* __restrict__ Wp, const float* __restrict__ bp,
            const float* __restrict__ Wg, const float* __restrict__ bg)
{
    __shared__ __half Ws[384 * 40];
    __shared__ __half Xs[64 * 40];

    const int tid  = threadIdx.x;
    const int w    = tid >> 5;
    const int lane = tid & 31;
    const int g = lane >> 2, t = lane & 3;
    const int b  = blockIdx.y;
    const int n0 = blockIdx.x * 64;
    const int mw = w & 3;
    const int ow = w >> 2;

    float acc[24][4];
#pragma unroll
    for (int i = 0; i < 24; i++) { acc[i][0]=acc[i][1]=acc[i][2]=acc[i][3]=0.f; }

    for (int kc = 0; kc < CH; kc += 32) {
        __syncthreads();
#pragma unroll
        for (int it = 0; it < 24; it++) {
            int p = tid + 256 * it;
            int row = p >> 4, c2 = p & 15;
            const float* src; int r = row;
            if (row < 128)      { src = Wt; }
            else if (row < 256) { src = Wp; r = row - 128; }
            else                { src = Wg; r = row - 256; }
            float2 v = *reinterpret_cast<const float2*>(&src[r * CH + kc + 2 * c2]);
            *reinterpret_cast<uint32_t*>(&Ws[row * 40 + 2 * c2]) = packh2(v.x, v.y);
        }
#pragma unroll
        for (int it = 0; it < 4; it++) {
            int p = tid + 256 * it;
            int cl = p >> 5, j2 = p & 31;
            float2 v = *reinterpret_cast<const float2*>(
                &x[((size_t)(b * CH + kc + cl)) * NPOS + n0 + 2 * j2]);
            Xs[(2 * j2)     * 40 + cl] = __float2half_rn(v.x);
            Xs[(2 * j2 + 1) * 40 + cl] = __float2half_rn(v.y);
        }
        __syncthreads();
#pragma unroll
        for (int ks = 0; ks < 2; ks++) {
            uint32_t a[4];
            int base = (mw * 16 + g) * 40 + ks * 16 + 2 * t;
            a[0] = *reinterpret_cast<const uint32_t*>(&Xs[base]);
            a[1] = *reinterpret_cast<const uint32_t*>(&Xs[base + 8 * 40]);
            a[2] = *reinterpret_cast<const uint32_t*>(&Xs[base + 8]);
            a[3] = *reinterpret_cast<const uint32_t*>(&Xs[base + 8 * 40 + 8]);
#pragma unroll
            for (int i = 0; i < 24; i++) {
                int ocr = (ow * 24 + i) * 8 + g;
                uint32_t b0 = *reinterpret_cast<const uint32_t*>(&Ws[ocr * 40 + ks * 16 + 2 * t]);
                uint32_t b1 = *reinterpret_cast<const uint32_t*>(&Ws[ocr * 40 + ks * 16 + 2 * t + 8]);
                mma16816(acc[i], a, b0, b1);
            }
        }
    }
    const int row_lo = n0 + mw * 16 + g;
    const int row_hi = row_lo + 8;
#pragma unroll
    for (int i = 0; i < 24; i++) {
        int col0 = ow * 192 + i * 8 + 2 * t;
        int arr  = col0 >> 7;
        int ch   = col0 & 127;
        const float* bias = (arr == 0) ? bt : (arr == 1) ? bp : bg;
        float b0v = bias[ch], b1v = bias[ch + 1];
        float v0 = acc[i][0] + b0v, v1 = acc[i][1] + b1v;
        float v2 = acc[i][2] + b0v, v3 = acc[i][3] + b1v;
        if (arr == 2) {
            size_t base = ((size_t)b * CI + ch) * NPOS;
            Vg[base + row_lo]        = __float2half_rn(v0);
            Vg[base + NPOS + row_lo] = __float2half_rn(v1);
            Vg[base + row_hi]        = __float2half_rn(v2);
            Vg[base + NPOS + row_hi] = __float2half_rn(v3);
        } else {
            __half* dst = (arr == 0) ? Qg : Kg2;
            *reinterpret_cast<uint32_t*>(&dst[((size_t)b * NPOS + row_lo) * CI + ch]) = packh2(v0, v1);
            *reinterpret_cast<uint32_t*>(&dst[((size_t)b * NPOS + row_hi) * CI + ch]) = packh2(v2, v3);
        }
    }
}

// ============================================================================
// Kernel 2: flash attention, kv-split warp pairs.
// 256 threads (8 warps). Pair p = w>>1 owns q rows [q0+32p, +32); half h = w&1
// owns kv columns [32h, 32h+32) of each 64-wide KV tile. 2 warps/SMSP.
// 3-stage cp.async pipeline, ONE barrier per tile: wait -> sync -> issue
// refill of tile kt+2 into the stage freed by kt-1 -> compute (no tail sync).
// ============================================================================
__global__ void __launch_bounds__(256)
attn_kernel()
{
    extern __shared__ __half sm[];   // [Qs 128x136][stage0][stage1][stage2]

    const int tid  = threadIdx.x;
    const int w    = tid >> 5;
    const int lane = tid & 31;
    const int g = lane >> 2, t = lane & 3;
    const int pair = w >> 1, h = w & 1;
    const int b  = blockIdx.y;
    const int q0 = blockIdx.x * 128;
    const size_t bN = (size_t)b * NPOS;

    const uint32_t sm_s = (uint32_t)__cvta_generic_to_shared(sm);

    // ldmatrix per-thread row offsets (bytes)
    const int mrow = lane >> 3, r8 = lane & 7;
    const uint32_t offA = (uint32_t)(((mrow & 1) * 8 + r8) * 272 + (mrow >> 1) * 16);
    const uint32_t offB = (uint32_t)(((mrow >> 1) * 8 + r8) * 272 + (mrow & 1) * 16);
    const uint32_t offV = (uint32_t)(((mrow >> 1) * 8 + r8) * 144 + (mrow & 1) * 16);

    // ---- async-load Q tile (group 0): 128 rows x 16 chunks of 16B ----
#pragma unroll
    for (int i = 0; i < 8; i++) {
        int s_ = tid + 256 * i;
        int row = s_ >> 4, c = s_ & 15;
        cp16(sm_s + row * 272 + c * 16, &Qg[(bN + q0 + row) * CI + c * 8]);
    }
    cp_commit();

    // ---- prime stages 0,1 with tiles 0,1 (groups 1,2) ----
#pragma unroll
    for (int pre = 0; pre < 2; pre++) {
        uint32_t kb = sm_s + (QS_H + pre * STAGE_H) * 2;
        uint32_t vb = kb + KS_H * 2;
#pragma unroll
        for (int i = 0; i < 4; i++) {        // K: 64 rows x 16 chunks
            int s_ = tid + 256 * i;
            int row = s_ >> 4, c = s_ & 15;
            cp16(kb + row * 272 + c * 16, &Kg2[(bN + pre * 64 + row) * CI + c * 8]);
        }
#pragma unroll
        for (int i = 0; i < 4; i++) {        // V: 128 rows x 8 chunks
            int s_ = tid + 256 * i;
            int ci = s_ >> 3, c = s_ & 7;
            cp16(vb + ci * 144 + c * 16, &Vg[((size_t)b * CI + ci) * NPOS + pre * 64 + c * 8]);
        }
        cp_commit();
    }
    cp_wait2();          // Q resident
    __syncthreads();

    float Yacc[2][16][4];
#pragma unroll
    for (int s = 0; s < 2; s++)
#pragma unroll
        for (int i = 0; i < 16; i++) { Yacc[s][i][0]=Yacc[s][i][1]=Yacc[s][i][2]=Yacc[s][i][3]=0.f; }
    float dsum[2][2] = {{0.f, 0.f}, {0.f, 0.f}};

    const uint32_t qa_base = sm_s + pair * 32 * 272 + offA;   // + sub*4352 + kc*32

    int st = 0;                       // stage of tile kt (kt % 3)
    for (int kt = 0; kt < NBLK; kt++) {
        uint32_t kstage = sm_s + (QS_H + st * STAGE_H) * 2;
        uint32_t vstage = kstage + KS_H * 2;
        const uint32_t kb_base = kstage + h * 32 * 272 + offB;
        const uint32_t vb_base = vstage + (h * 32) * 2 + offV;

        if (kt < NBLK - 1) cp_wait1(); else cp_wait0();   // tile kt resident
        __syncthreads();   // also: all warps finished tile kt-1 -> its stage is free

        if (kt + 2 < NBLK) {   // refill tile kt+2 into stage (kt+2)%3 == stage of kt-1
            int rs = st + 2; if (rs >= NSTAGE) rs -= NSTAGE;
            uint32_t kb = sm_s + (QS_H + rs * STAGE_H) * 2;
            uint32_t vb = kb + KS_H * 2;
#pragma unroll
            for (int i = 0; i < 4; i++) {    // K: 64 rows x 16 chunks
                int s_ = tid + 256 * i;
                int row = s_ >> 4, c = s_ & 15;
                cp16(kb + row * 272 + c * 16, &Kg2[(bN + (kt + 2) * 64 + row) * CI + c * 8]);
            }
#pragma unroll
            for (int i = 0; i < 4; i++) {    // V: 128 rows x 8 chunks
                int s_ = tid + 256 * i;
                int ci = s_ >> 3, c = s_ & 7;
                cp16(vb + ci * 144 + c * 16, &Vg[((size_t)b * CI + ci) * NPOS + (kt + 2) * 64 + c * 8]);
            }
            cp_commit();
        }

        // ---- S = Q K^T over this warp's kv half (n32) ----
        float S2[2][4][4];
#pragma unroll
        for (int s = 0; s < 2; s++)
#pragma unroll
            for (int nb = 0; nb < 4; nb++) { S2[s][nb][0]=S2[s][nb][1]=S2[s][nb][2]=S2[s][nb][3]=0.f; }
#pragma unroll
        for (int kc = 0; kc < 8; kc++) {
            uint32_t A0[4], A1[4], B0[4], B1[4];
            ldsm4(A0, qa_base + kc * 32);
            ldsm4(A1, qa_base + 4352 + kc * 32);
            ldsm4(B0, kb_base + kc * 32);
            ldsm4(B1, kb_base + 4352 + kc * 32);
            mma16816(S2[0][0], A0, B0[0], B0[1]);
            mma16816(S2[0][1], A0, B0[2], B0[3]);
            mma16816(S2[0][2], A0, B1[0], B1[1]);
            mma16816(S2[0][3], A0, B1[2], B1[3]);
            mma16816(S2[1][0], A1, B0[0], B0[1]);
            mma16816(S2[1][1], A1, B0[2], B0[3]);
            mma16816(S2[1][2], A1, B1[0], B1[1]);
            mma16816(S2[1][3], A1, B1[2], B1[3]);
        }

        // ---- P = exp(S); pack into PV A-frags; accumulate row sums ----
        uint32_t Ap[2][2][4];
#pragma unroll
        for (int s = 0; s < 2; s++) {
#pragma unroll
            for (int nb = 0; nb < 4; nb++) {
                float e0 = __expf(S2[s][nb][0]), e1 = __expf(S2[s][nb][1]);
                float e2 = __expf(S2[s][nb][2]), e3 = __expf(S2[s][nb][3]);
                dsum[s][0] += e0 + e1;
                dsum[s][1] += e2 + e3;
                int j = nb >> 1;
                if ((nb & 1) == 0) {
                    Ap[s][j][0] = packh2(e0, e1);
                    Ap[s][j][1] = packh2(e2, e3);
                } else {
                    Ap[s][j][2] = packh2(e0, e1);
                    Ap[s][j][3] = packh2(e2, e3);
                }
            }
        }

        // ---- Y += P V over this warp's kv half (k32) ----
#pragma unroll
        for (int j = 0; j < 2; j++) {
#pragma unroll
            for (int ctg = 0; ctg < 8; ctg++) {
                uint32_t Bv[4];
                ldsm4(Bv, vb_base + j * 32 + ctg * 2304);
                mma16816(Yacc[0][2 * ctg],     Ap[0][j], Bv[0], Bv[1]);
                mma16816(Yacc[0][2 * ctg + 1], Ap[0][j], Bv[2], Bv[3]);
                mma16816(Yacc[1][2 * ctg],     Ap[1][j], Bv[0], Bv[1]);
                mma16816(Yacc[1][2 * ctg + 1], Ap[1][j], Bv[2], Bv[3]);
            }
        }
        // no tail barrier: next iteration's sync protects stage reuse

        st++; if (st >= NSTAGE) st = 0;
    }
    __syncthreads();   // all warps done with last tile before smem aliasing below

    // ---- intra-warp row sums over t ----
#pragma unroll
    for (int s = 0; s < 2; s++)
#pragma unroll
        for (int hl = 0; hl < 2; hl++) {
            dsum[s][hl] += __shfl_xor_sync(0xffffffffu, dsum[s][hl], 1);
            dsum[s][hl] += __shfl_xor_sync(0xffffffffu, dsum[s][hl], 2);
        }

    // ---- combine kv halves through smem (stages no longer needed) ----
    float* smf = reinterpret_cast<float*>(sm);
    if (h == 1) {
#pragma unroll
        for (int s = 0; s < 2; s++)
#pragma unroll
            for (int ct = 0; ct < 16; ct++)
#pragma unroll
                for (int i = 0; i < 4; i++)
                    smf[pair * 4096 + ((s * 16 + ct) * 4 + i) * 32 + lane] = Yacc[s][ct][i];
        if (t == 0) {
#pragma unroll
            for (int s = 0; s < 2; s++) {
                smf[16384 + pair * 32 + s * 16 + g]     = dsum[s][0];
                smf[16384 + pair * 32 + s * 16 + 8 + g] = dsum[s][1];
            }
        }
    }
    __syncthreads();
    if (h == 0) {
#pragma unroll
        for (int s = 0; s < 2; s++) {
            float dl = dsum[s][0] + smf[16384 + pair * 32 + s * 16 + g];
            float dh = dsum[s][1] + smf[16384 + pair * 32 + s * 16 + 8 + g];
            float rlo = 1.f / dl, rhi = 1.f / dh;
            size_t olo = (bN + q0 + pair * 32 + s * 16 + g) * CI;
            size_t ohi = olo + (size_t)8 * CI;
#pragma unroll
            for (int ct = 0; ct < 16; ct++) {
                int base = pair * 4096 + ((s * 16 + ct) * 4) * 32 + lane;
                float y0 = Yacc[s][ct][0] + smf[base];
                float y1 = Yacc[s][ct][1] + smf[base + 32];
                float y2 = Yacc[s][ct][2] + smf[base + 64];
                float y3 = Yacc[s][ct][3] + smf[base + 96];
                int ch = ct * 8 + 2 * t;
                *reinterpret_cast<uint32_t*>(&Yg[olo + ch]) = packh2(y0 * rlo, y1 * rlo);
                *reinterpret_cast<uint32_t*>(&Yg[ohi + ch]) = packh2(y2 * rhi, y3 * rhi);
            }
        }
    }
}

// ============================================================================
// Kernel 3: wy = Ww @ y + bw -> wyg, plus per-block BN partials
// (partials stored transposed [c][blk] for coalesced bnstats).
// ============================================================================
__global__ void __launch_bounds__(256)
wproj_kernel(const float* __restrict__ Ww, const float* __restrict__ bw)
{
    __shared__ __half Ys[64 * 136];
    __shared__ __half Ws2[256 * 40];
    __shared__ float  ps[4][256];
    __shared__ float  pq[4][256];

    const int tid  = threadIdx.x;
    const int w    = tid >> 5;
    const int lane = tid & 31;
    const int g = lane >> 2, t = lane & 3;
    const int b  = blockIdx.y;
    const int n0 = blockIdx.x * 64;
    const int mw = w & 3;
    const int ow = w >> 2;

    {
        int row = tid >> 2, off = (tid & 3) * 32;
        const uint4* src = reinterpret_cast<const uint4*>(&Yg[((size_t)b * NPOS + n0 + row) * CI + off]);
        uint4* dst = reinterpret_cast<uint4*>(&Ys[row * 136 + off]);
#pragma unroll
        for (int i = 0; i < 4; i++) dst[i] = src[i];
    }

    float acc[16][4];
#pragma unroll
    for (int i = 0; i < 16; i++) { acc[i][0]=acc[i][1]=acc[i][2]=acc[i][3]=0.f; }

    for (int kc = 0; kc < CI; kc += 32) {
        __syncthreads();
#pragma unroll
        for (int it = 0; it < 16; it++) {
            int p = tid + 256 * it;
            int oc = p >> 4, c2 = p & 15;
            float2 v = *reinterpret_cast<const float2*>(&Ww[oc * CI + kc + 2 * c2]);
            *reinterpret_cast<uint32_t*>(&Ws2[oc * 40 + 2 * c2]) = packh2(v.x, v.y);
        }
        __syncthreads();
#pragma unroll
        for (int ks = 0; ks < 2; ks++) {
            uint32_t a[4];
            int base = (mw * 16 + g) * 136 + kc + ks * 16 + 2 * t;
            a[0] = *reinterpret_cast<const uint32_t*>(&Ys[base]);
            a[1] = *reinterpret_cast<const uint32_t*>(&Ys[base + 8 * 136]);
            a[2] = *reinterpret_cast<const uint32_t*>(&Ys[base + 8]);
            a[3] = *reinterpret_cast<const uint32_t*>(&Ys[base + 8 * 136 + 8]);
#pragma unroll
            for (int i = 0; i < 16; i++) {
                int ocr = (ow * 16 + i) * 8 + g;
                uint32_t b0 = *reinterpret_cast<const uint32_t*>(&Ws2[ocr * 40 + ks * 16 + 2 * t]);
                uint32_t b1 = *reinterpret_cast<const uint32_t*>(&Ws2[ocr * 40 + ks * 16 + 2 * t + 8]);
                mma16816(acc[i], a, b0, b1);
            }
        }
    }
    const int row_lo = n0 + mw * 16 + g;
    const int row_hi = row_lo + 8;
#pragma unroll
    for (int i = 0; i < 16; i++) {
        int oc0 = ow * 128 + i * 8 + 2 * t;
        float bw0 = bw[oc0], bw1 = bw[oc0 + 1];
        float v0 = acc[i][0] + bw0, v1 = acc[i][1] + bw1;
        float v2 = acc[i][2] + bw0, v3 = acc[i][3] + bw1;
        size_t base = ((size_t)b * CH + oc0) * NPOS;
        wyg[base + row_lo]        = v0;
        wyg[base + NPOS + row_lo] = v1;
        wyg[base + row_hi]        = v2;
        wyg[base + NPOS + row_hi] = v3;
        float s0 = v0 + v2, s1 = v1 + v3;
        float q0s = v0 * v0 + v2 * v2, q1s = v1 * v1 + v3 * v3;
#pragma unroll
        for (int m = 4; m <= 16; m <<= 1) {
            s0  += __shfl_xor_sync(0xffffffffu, s0, m);
            s1  += __shfl_xor_sync(0xffffffffu, s1, m);
            q0s += __shfl_xor_sync(0xffffffffu, q0s, m);
            q1s += __shfl_xor_sync(0xffffffffu, q1s, m);
        }
        if (lane < 4) {
            int oc = ow * 128 + i * 8 + 2 * lane;
            ps[mw][oc] = s0;  ps[mw][oc + 1] = s1;
            pq[mw][oc] = q0s; pq[mw][oc + 1] = q1s;
        }
    }
    __syncthreads();
    {
        float s = ps[0][tid] + ps[1][tid] + ps[2][tid] + ps[3][tid];
        float q = pq[0][tid] + pq[1][tid] + pq[2][tid] + pq[3][tid];
        int blk = blockIdx.y * NBLK + blockIdx.x;
        psum_g[tid * (BATCH * NBLK) + blk] = s;   // [c][blk]
        psq_g [tid * (BATCH * NBLK) + blk] = q;
    }
}

// ============================================================================
// Kernel 4: BN stats. One block per channel; coalesced reads; fixed-order tree.
// ============================================================================
__global__ void __launch_bounds__(256)
bnstats_kernel(const float* __restrict__ gamma,
               const float* __restrict__ beta)
{
    __shared__ float ss[256];
    __shared__ float qq[256];
    const int c = blockIdx.x, tid = threadIdx.x;
    ss[tid] = psum_g[c * 256 + tid];
    qq[tid] = psq_g [c * 256 + tid];
    __syncthreads();
#pragma unroll
    for (int m = 128; m > 0; m >>= 1) {
        if (tid < m) { ss[tid] += ss[tid + m]; qq[tid] += qq[tid + m]; }
        __syncthreads();
    }
    if (tid == 0) {
        const float inv = 1.f / (float)(BATCH * NPOS);
        float mean = ss[0] * inv;
        float var  = qq[0] * inv - mean * mean;
        float sc = gamma[c] * rsqrtf(var + 1e-5f);
        scale_g[c] = sc;
        shift_g[c] = beta[c] - mean * sc;
    }
}

// ============================================================================
// Kernel 5: out = wy * scale + shift + x
// ============================================================================
__global__ void __launch_bounds__(256)
final_kernel(const float* __restrict__ x, float* __restrict__ out)
{
    size_t e = ((size_t)blockIdx.x * 256 + threadIdx.x) * 4;
    int c = (int)((e >> 13) & 255);
    float4 wv = *reinterpret_cast<const float4*>(&wyg[e]);
    float4 xv = *reinterpret_cast<const float4*>(&x[e]);
    float sc = scale_g[c], sh = shift_g[c];
    float4 o;
    o.x = wv.x * sc + sh + xv.x;
    o.y = wv.y * sc + sh + xv.y;
    o.z = wv.z * sc + sh + xv.z;
    o.w = wv.w * sc + sh + xv.w;
    *reinterpret_cast<float4*>(&out[e]) = o;
}

// ============================================================================
extern "C" void kernel_launch(void* const* d_in, const int* in_sizes, int n_in,
                              void* d_out, int out_size)
{
    const float* x     = (const float*)d_in[0];
    const float* Wt    = (const float*)d_in[1];
    const float* bt    = (const float*)d_in[2];
    const float* Wp    = (const float*)d_in[3];
    const float* bp    = (const float*)d_in[4];
    const float* Wg    = (const float*)d_in[5];
    const float* bg    = (const float*)d_in[6];
    const float* Ww    = (const float*)d_in[7];
    const float* bw    = (const float*)d_in[8];
    const float* gamma = (const float*)d_in[9];
    const float* beta  = (const float*)d_in[10];
    float* out = (float*)d_out;

    cudaFuncSetAttribute(attn_kernel,
                         cudaFuncAttributeMaxDynamicSharedMemorySize,
                         ATTN_SMEM_BYTES);

    proj_kernel<<<dim3(NBLK, BATCH), 256>>>(x, Wt, bt, Wp, bp, Wg, bg);
    attn_kernel<<<dim3(NPOS / 128, BATCH), 256, ATTN_SMEM_BYTES>>>();
    wproj_kernel<<<dim3(NBLK, BATCH), 256>>>(Ww, bw);
    bnstats_kernel<<<CH, 256>>>(gamma, beta);
    final_kernel<<<(BATCH * CH * NPOS) / (256 * 4), 256>>>(x, out);
}